// round 7
// baseline (speedup 1.0000x reference)
#include <cuda_runtime.h>
#include <cuda_bf16.h>
#include <cstdint>

// ---------------------------------------------------------------------------
// SO3Linear (L=3, B=1024, C=256) via bf16 split-precision mma.sync GEMM.
//
//  K0 setup_offsets : contiguous range tables from seg1/seg2 (nondecreasing)
//  K1 wsplit        : W[w][ci][co] fp32 -> g_wx[w][co][kc][hi 64B | lo 64B]
//  K2 build_inter   : inter fp32 -> g_ax[(g,b)][kc][hi 64B | lo 64B]
//  K3 so3_mma       : per CTA (64 b-rows, 128 co, order M):
//                     fp32 accum of sum_g [Ah@Wh + Al@Wh + Ah@Wl]
//                     KT=32, 2-stage cp.async, 3 CTAs/SM, heavy-M-first.
// ---------------------------------------------------------------------------

#define NORD     16
#define CI       256
#define CO       256
#define G_MAX    156
#define NNZ_MAX  512
#define NW_MAX   40
#define B_MAX    1024

// interleaved layouts: per (row) 8 k-chunks x 128B, each 128B = hi(64B)|lo(64B)
__device__ __nv_bfloat16 g_ax[(size_t)G_MAX * B_MAX * CI * 2];
__device__ __nv_bfloat16 g_wx[(size_t)NW_MAX * CO * CI * 2];
__device__ int g_gs[G_MAX + 1];
__device__ int g_mg[NORD + 1];

// heavy-orders-first schedule (groups/M: l=2 ->11, l=3 ->10, l=1 ->9, l=0 ->4)
__constant__ int c_morder[NORD] = {4,5,6,7,8, 9,10,11,12,13,14,15, 1,2,3, 0};

#define SWZ(o) ((o) ^ (((o) >> 3) & 0x70))

__device__ __forceinline__ uint32_t smem_u32(const void* p) {
    uint32_t a;
    asm("{ .reg .u64 t; cvta.to.shared.u64 t, %1; cvt.u32.u64 %0, t; }" : "=r"(a) : "l"(p));
    return a;
}
__device__ __forceinline__ void cp16(uint32_t dst, const void* src) {
    asm volatile("cp.async.cg.shared.global [%0], [%1], 16;" :: "r"(dst), "l"(src) : "memory");
}
#define CP_COMMIT()  asm volatile("cp.async.commit_group;" ::: "memory")
#define CP_WAIT(N)   asm volatile("cp.async.wait_group %0;" :: "n"(N) : "memory")

__device__ __forceinline__ void ldsm4(uint32_t r[4], uint32_t addr) {
    asm volatile("ldmatrix.sync.aligned.m8n8.x4.shared.b16 {%0,%1,%2,%3}, [%4];"
                 : "=r"(r[0]), "=r"(r[1]), "=r"(r[2]), "=r"(r[3]) : "r"(addr));
}
__device__ __forceinline__ void mma16816(float c[4], const uint32_t a[4],
                                         uint32_t b0, uint32_t b1) {
    asm volatile(
        "mma.sync.aligned.m16n8k16.row.col.f32.bf16.bf16.f32 "
        "{%0,%1,%2,%3}, {%4,%5,%6,%7}, {%8,%9}, {%0,%1,%2,%3};"
        : "+f"(c[0]), "+f"(c[1]), "+f"(c[2]), "+f"(c[3])
        : "r"(a[0]), "r"(a[1]), "r"(a[2]), "r"(a[3]), "r"(b0), "r"(b1));
}

// ---------------------------------------------------------------------------
// K0: range tables
// ---------------------------------------------------------------------------
__global__ void setup_offsets(const int* __restrict__ seg1,
                              const int* __restrict__ seg2,
                              int nnz, int G) {
    int tid = threadIdx.x;
    for (int i = tid; i < nnz; i += blockDim.x) {
        if (i == 0) g_gs[seg1[0]] = 0;
        else if (seg1[i] != seg1[i - 1]) g_gs[seg1[i]] = i;
    }
    for (int i = tid; i < G; i += blockDim.x) {
        if (i == 0) g_mg[seg2[0]] = 0;
        else if (seg2[i] != seg2[i - 1]) g_mg[seg2[i]] = i;
    }
    if (tid == 0) { g_gs[G] = nnz; g_mg[NORD] = G; }
}

// ---------------------------------------------------------------------------
// K1: transpose + split weights into interleaved layout
//     g_wx[((w*CO+co)*8 + ci/32)*64 + 0..31] = hi, +32.. = lo (bf16 units)
// ---------------------------------------------------------------------------
__global__ __launch_bounds__(256) void wsplit(const float* __restrict__ weight) {
    __shared__ float tile[32][33];
    const int w  = blockIdx.z;
    const int bx = blockIdx.x;   // co block
    const int by = blockIdx.y;   // ci block
    const int tx = threadIdx.x & 31;
    const int ty = threadIdx.x >> 5;

    const float* in = weight + (size_t)w * CI * CO;
#pragma unroll
    for (int j = 0; j < 4; ++j) {
        int r = ty + 8 * j;
        tile[r][tx] = in[(size_t)(by * 32 + r) * CO + bx * 32 + tx];
    }
    __syncthreads();
#pragma unroll
    for (int j = 0; j < 4; ++j) {
        int r = ty + 8 * j;                 // local co
        float v = tile[tx][r];              // (ci=by*32+tx, co=bx*32+r)
        __nv_bfloat16 h = __float2bfloat16(v);
        float lo = v - __bfloat162float(h);
        const int co = bx * 32 + r;
        const int ci = by * 32 + tx;
        size_t o = (((size_t)w * CO + co) * 8 + (ci >> 5)) * 64 + (ci & 31);
        g_wx[o]      = h;
        g_wx[o + 32] = __float2bfloat16(lo);
    }
}

// ---------------------------------------------------------------------------
// K2: build inter (vectorized, g-split x4). Block = 4 b; thread owns 4 ci.
// Writes interleaved hi|lo rows.
// ---------------------------------------------------------------------------
__global__ __launch_bounds__(256) void build_inter(
    const float* __restrict__ x,
    const float* __restrict__ sh,
    const float* __restrict__ CG,
    const int* __restrict__ M1,
    const int* __restrict__ M2,
    int nnz, int G, int Bn) {

    __shared__ float coefs4[4][NNZ_MAX];
    __shared__ int   m1s[NNZ_MAX];
    __shared__ int   gs_s[G_MAX + 1];

    const int b_base = blockIdx.x * 4;
    const int q      = blockIdx.y;
    const int tid    = threadIdx.x;
    const int bsub   = tid >> 6;          // 0..3
    const int c4     = (tid & 63) * 4;    // ci base

    const int gq0 = (G * q) >> 2;
    const int gq1 = (G * (q + 1)) >> 2;

    for (int i = tid; i <= G; i += 256) gs_s[i] = g_gs[i];
    __syncthreads();
    const int n0 = gs_s[gq0];
    const int n1 = gs_s[gq1];

    for (int i = n0 + tid; i < n1; i += 256) m1s[i] = M1[i] * CI;
#pragma unroll
    for (int bb = 0; bb < 4; ++bb) {
        const float* shb = sh + (size_t)(b_base + bb) * NORD;
        for (int i = n0 + tid; i < n1; i += 256)
            coefs4[bb][i] = CG[i] * shb[M2[i]];
    }
    __syncthreads();

    const int b = b_base + bsub;
    const float* xb = x + (size_t)b * NORD * CI + c4;
    const float* cf = coefs4[bsub];

    for (int g = gq0; g < gq1; ++g) {
        float ax = 0.f, ay = 0.f, az = 0.f, aw = 0.f;
        const int e = gs_s[g + 1];
        for (int idx = gs_s[g]; idx < e; ++idx) {
            const float c = cf[idx];
            const float4 xv = *reinterpret_cast<const float4*>(xb + m1s[idx]);
            ax = fmaf(c, xv.x, ax);
            ay = fmaf(c, xv.y, ay);
            az = fmaf(c, xv.z, az);
            aw = fmaf(c, xv.w, aw);
        }
        __nv_bfloat162 h01 = __floats2bfloat162_rn(ax, ay);
        __nv_bfloat162 h23 = __floats2bfloat162_rn(az, aw);
        float lx = ax - __bfloat162float(__low2bfloat16(h01));
        float ly = ay - __bfloat162float(__high2bfloat16(h01));
        float lz = az - __bfloat162float(__low2bfloat16(h23));
        float lw = aw - __bfloat162float(__high2bfloat16(h23));
        __nv_bfloat162 l01 = __floats2bfloat162_rn(lx, ly);
        __nv_bfloat162 l23 = __floats2bfloat162_rn(lz, lw);

        // interleaved row: ((g*Bn+b)*8 + c4/32)*64 + (c4&31), lo at +32
        size_t o = (((size_t)g * Bn + b) * 8 + (c4 >> 5)) * 64 + (c4 & 31);
        *reinterpret_cast<uint2*>(g_ax + o) =
            make_uint2(*(uint32_t*)&h01, *(uint32_t*)&h23);
        *reinterpret_cast<uint2*>(g_ax + o + 32) =
            make_uint2(*(uint32_t*)&l01, *(uint32_t*)&l23);
    }
}

// ---------------------------------------------------------------------------
// K3: mma.sync GEMM. Grid (Bn/64, CO/128, NORD), 256 threads (4m x 2n warps).
// Block tile 64(b) x 128(co), KT=32. Stage 24KB: A 8K | W 16K.
// Row layout (128B, SW128): hi 32k (64B) | lo 32k (64B).
// 2 stages = 48KB -> 3 CTAs/SM.
// ---------------------------------------------------------------------------
#define OFF_W       8192
#define STAGE_BYTES 24576
#define SMEM_DYN    (2 * STAGE_BYTES + 1024)

__device__ __forceinline__ void load_stage(uint32_t st,
                                           const char* gA, const char* gW,
                                           int tid) {
    // A: 64 rows x 8 chunks of 16B (row = 128B interleaved hi|lo)
#pragma unroll
    for (int i = 0; i < 2; ++i) {
        int idx = tid + i * 256;
        int r = idx >> 3, c = idx & 7;
        cp16(st + SWZ(r * 128 + c * 16), gA + (size_t)r * 1024 + c * 16);
    }
    // W: 128 rows x 8 chunks
#pragma unroll
    for (int i = 0; i < 4; ++i) {
        int idx = tid + i * 256;
        int r = idx >> 3, c = idx & 7;
        cp16(st + OFF_W + SWZ(r * 128 + c * 16), gW + (size_t)r * 1024 + c * 16);
    }
}

__global__ __launch_bounds__(256, 3) void so3_mma(
    const int* __restrict__ l_ind,
    float* __restrict__ out,
    int Bn) {

    extern __shared__ char smem[];
    const uint32_t sb   = smem_u32(smem);
    const uint32_t base = (sb + 1023) & ~1023u;

    const int tid  = threadIdx.x;
    const int wid  = tid >> 5;
    const int lane = tid & 31;
    const int wm   = wid & 3;          // 4 m-warps (16 rows each)
    const int wn   = wid >> 2;         // 2 n-warps (64 cols each)

    const int b0  = blockIdx.x * 64;
    const int cob = blockIdx.y * 128;
    const int M   = c_morder[blockIdx.z];
    const int gbeg = g_mg[M];
    const int gend = g_mg[M + 1];
    const int T = (gend - gbeg) * 8;   // k-chunks of 32

    float acc[8][4];
#pragma unroll
    for (int j = 0; j < 8; ++j)
#pragma unroll
        for (int q = 0; q < 4; ++q) acc[j][q] = 0.f;

    auto srcA = [&](int t) -> const char* {
        int g = gbeg + (t >> 3), kc = t & 7;
        return (const char*)g_ax + ((size_t)g * Bn + b0) * 1024 + kc * 128;
    };
    auto srcW = [&](int t) -> const char* {
        int g = gbeg + (t >> 3), kc = t & 7;
        int w = __ldg(l_ind + g);
        return (const char*)g_wx + ((size_t)w * CO + cob) * 1024 + kc * 128;
    };

    load_stage(base, srcA(0), srcW(0), tid);
    CP_COMMIT();

    const int arow = wm * 16 + (lane & 15);
    const int acol = (lane >> 4) * 16;
    const int wrow = wn * 64 + (lane & 7) + ((lane >> 4) << 3);
    const int wcol = ((lane >> 3) & 1) * 16;

    for (int t = 0; t < T; ++t) {
        const uint32_t st = base + (uint32_t)(t & 1) * STAGE_BYTES;

        if (t + 1 < T) {
            const uint32_t stn = base + (uint32_t)((t + 1) & 1) * STAGE_BYTES;
            load_stage(stn, srcA(t + 1), srcW(t + 1), tid);
            CP_COMMIT();
            CP_WAIT(1);
        } else {
            CP_WAIT(0);
        }
        __syncthreads();

#pragma unroll
        for (int ks = 0; ks < 2; ++ks) {           // two k16 steps in KT=32
            const int kb = ks * 32;                // byte offset in hi half
            uint32_t ah[4], al[4];
            {
                uint32_t ad = st + SWZ(arow * 128 + kb + acol);
                ldsm4(ah, ad);
                ldsm4(al, ad ^ 64);                // lo half of the row
            }
#pragma unroll
            for (int j = 0; j < 4; ++j) {
                uint32_t whf[4], wlf[4];
                uint32_t wd = st + OFF_W + SWZ((wrow + j * 16) * 128 + kb + wcol);
                ldsm4(whf, wd);
                ldsm4(wlf, wd ^ 64);
#pragma unroll
                for (int s = 0; s < 2; ++s) {
                    float* c = acc[j * 2 + s];
                    mma16816(c, ah, whf[s * 2], whf[s * 2 + 1]);
                    mma16816(c, al, whf[s * 2], whf[s * 2 + 1]);
                    mma16816(c, ah, wlf[s * 2], wlf[s * 2 + 1]);
                }
            }
        }
        __syncthreads();
    }

    // epilogue: out[b0+.., M, cob+..] written exactly once
    const int m0 = b0 + wm * 16 + (lane >> 2);
#pragma unroll
    for (int j = 0; j < 8; ++j) {
        const int n = cob + wn * 64 + j * 8 + (lane & 3) * 2;
        float* p0 = out + ((size_t)m0 * NORD + M) * CO + n;
        float* p1 = out + ((size_t)(m0 + 8) * NORD + M) * CO + n;
        *(float2*)p0 = make_float2(acc[j][0], acc[j][1]);
        *(float2*)p1 = make_float2(acc[j][2], acc[j][3]);
    }
}

// ---------------------------------------------------------------------------
// Inputs: x, sh, weight, CG_vals, M1, M2, seg1, l_ind, seg2, num_orders_out
// ---------------------------------------------------------------------------
extern "C" void kernel_launch(void* const* d_in, const int* in_sizes, int n_in,
                              void* d_out, int out_size) {
    const float* x      = (const float*)d_in[0];
    const float* sh     = (const float*)d_in[1];
    const float* weight = (const float*)d_in[2];
    const float* CG     = (const float*)d_in[3];
    const int*   M1     = (const int*)d_in[4];
    const int*   M2     = (const int*)d_in[5];
    const int*   seg1   = (const int*)d_in[6];
    const int*   l_ind  = (const int*)d_in[7];
    const int*   seg2   = (const int*)d_in[8];
    float*       out    = (float*)d_out;

    const int nnz = in_sizes[4];
    const int G   = in_sizes[7];
    const int Bn  = in_sizes[1] / NORD;
    const int n_w = in_sizes[2] / (CI * CO);

    static bool attr_set = false;
    if (!attr_set) {
        cudaFuncSetAttribute(so3_mma, cudaFuncAttributeMaxDynamicSharedMemorySize, SMEM_DYN);
        attr_set = true;
    }

    setup_offsets<<<1, 256>>>(seg1, seg2, nnz, G);
    {
        dim3 grid(CO / 32, CI / 32, n_w);
        wsplit<<<grid, 256>>>(weight);
    }
    {
        dim3 grid(Bn / 4, 4);
        build_inter<<<grid, 256>>>(x, sh, CG, M1, M2, nnz, G, Bn);
    }
    {
        dim3 grid(Bn / 64, CO / 128, NORD);
        so3_mma<<<grid, 256, SMEM_DYN>>>(l_ind, out, Bn);
    }
}

// round 8
// speedup vs baseline: 1.0059x; 1.0059x over previous
#include <cuda_runtime.h>
#include <cuda_bf16.h>
#include <cstdint>

// ---------------------------------------------------------------------------
// SO3Linear (L=3, B=1024, C=256) via bf16 split-precision mma.sync GEMM.
//
//  K0 setup_offsets : contiguous range tables from seg1/seg2 (nondecreasing)
//  K1 wsplit        : W[w][ci][co] fp32 -> g_wx[w][co][kc][hi 64B | lo 64B]
//  K2 build_inter   : inter fp32 -> g_ax[(g,b)][kc][hi 64B | lo 64B]
//  K3 so3_mma       : per CTA (64 b-rows, 128 co, order M):
//                     fp32 accum of sum_g [Ah@Wh + Al@Wh + Ah@Wl]
//                     KT=32, 3-stage ring / 1 sync per stage, 2m x 4n warps,
//                     3 CTAs/SM, heavy-M-first.
// ---------------------------------------------------------------------------

#define NORD     16
#define CI       256
#define CO       256
#define G_MAX    156
#define NNZ_MAX  512
#define NW_MAX   40
#define B_MAX    1024

// interleaved layouts: per row 8 k-chunks x 128B, each 128B = hi(64B)|lo(64B)
__device__ __nv_bfloat16 g_ax[(size_t)G_MAX * B_MAX * CI * 2];
__device__ __nv_bfloat16 g_wx[(size_t)NW_MAX * CO * CI * 2];
__device__ int g_gs[G_MAX + 1];
__device__ int g_mg[NORD + 1];

// heavy-orders-first schedule (groups/M: l=2 ->11, l=3 ->10, l=1 ->9, l=0 ->4)
__constant__ int c_morder[NORD] = {4,5,6,7,8, 9,10,11,12,13,14,15, 1,2,3, 0};

#define SWZ(o) ((o) ^ (((o) >> 3) & 0x70))

__device__ __forceinline__ uint32_t smem_u32(const void* p) {
    uint32_t a;
    asm("{ .reg .u64 t; cvta.to.shared.u64 t, %1; cvt.u32.u64 %0, t; }" : "=r"(a) : "l"(p));
    return a;
}
__device__ __forceinline__ void cp16(uint32_t dst, const void* src) {
    asm volatile("cp.async.cg.shared.global [%0], [%1], 16;" :: "r"(dst), "l"(src) : "memory");
}
#define CP_COMMIT()  asm volatile("cp.async.commit_group;" ::: "memory")
#define CP_WAIT(N)   asm volatile("cp.async.wait_group %0;" :: "n"(N) : "memory")

__device__ __forceinline__ void ldsm4(uint32_t r[4], uint32_t addr) {
    asm volatile("ldmatrix.sync.aligned.m8n8.x4.shared.b16 {%0,%1,%2,%3}, [%4];"
                 : "=r"(r[0]), "=r"(r[1]), "=r"(r[2]), "=r"(r[3]) : "r"(addr));
}
__device__ __forceinline__ void mma16816(float c[4], const uint32_t a[4],
                                         uint32_t b0, uint32_t b1) {
    asm volatile(
        "mma.sync.aligned.m16n8k16.row.col.f32.bf16.bf16.f32 "
        "{%0,%1,%2,%3}, {%4,%5,%6,%7}, {%8,%9}, {%0,%1,%2,%3};"
        : "+f"(c[0]), "+f"(c[1]), "+f"(c[2]), "+f"(c[3])
        : "r"(a[0]), "r"(a[1]), "r"(a[2]), "r"(a[3]), "r"(b0), "r"(b1));
}

// ---------------------------------------------------------------------------
// K0: range tables
// ---------------------------------------------------------------------------
__global__ void setup_offsets(const int* __restrict__ seg1,
                              const int* __restrict__ seg2,
                              int nnz, int G) {
    int tid = threadIdx.x;
    for (int i = tid; i < nnz; i += blockDim.x) {
        if (i == 0) g_gs[seg1[0]] = 0;
        else if (seg1[i] != seg1[i - 1]) g_gs[seg1[i]] = i;
    }
    for (int i = tid; i < G; i += blockDim.x) {
        if (i == 0) g_mg[seg2[0]] = 0;
        else if (seg2[i] != seg2[i - 1]) g_mg[seg2[i]] = i;
    }
    if (tid == 0) { g_gs[G] = nnz; g_mg[NORD] = G; }
}

// ---------------------------------------------------------------------------
// K1: transpose + split weights into interleaved layout
// ---------------------------------------------------------------------------
__global__ __launch_bounds__(256) void wsplit(const float* __restrict__ weight) {
    __shared__ float tile[32][33];
    const int w  = blockIdx.z;
    const int bx = blockIdx.x;   // co block
    const int by = blockIdx.y;   // ci block
    const int tx = threadIdx.x & 31;
    const int ty = threadIdx.x >> 5;

    const float* in = weight + (size_t)w * CI * CO;
#pragma unroll
    for (int j = 0; j < 4; ++j) {
        int r = ty + 8 * j;
        tile[r][tx] = in[(size_t)(by * 32 + r) * CO + bx * 32 + tx];
    }
    __syncthreads();
#pragma unroll
    for (int j = 0; j < 4; ++j) {
        int r = ty + 8 * j;                 // local co
        float v = tile[tx][r];
        __nv_bfloat16 h = __float2bfloat16(v);
        float lo = v - __bfloat162float(h);
        const int co = bx * 32 + r;
        const int ci = by * 32 + tx;
        size_t o = (((size_t)w * CO + co) * 8 + (ci >> 5)) * 64 + (ci & 31);
        g_wx[o]      = h;
        g_wx[o + 32] = __float2bfloat16(lo);
    }
}

// ---------------------------------------------------------------------------
// K2: build inter (vectorized, g-split x4)
// ---------------------------------------------------------------------------
__global__ __launch_bounds__(256) void build_inter(
    const float* __restrict__ x,
    const float* __restrict__ sh,
    const float* __restrict__ CG,
    const int* __restrict__ M1,
    const int* __restrict__ M2,
    int nnz, int G, int Bn) {

    __shared__ float coefs4[4][NNZ_MAX];
    __shared__ int   m1s[NNZ_MAX];
    __shared__ int   gs_s[G_MAX + 1];

    const int b_base = blockIdx.x * 4;
    const int q      = blockIdx.y;
    const int tid    = threadIdx.x;
    const int bsub   = tid >> 6;
    const int c4     = (tid & 63) * 4;

    const int gq0 = (G * q) >> 2;
    const int gq1 = (G * (q + 1)) >> 2;

    for (int i = tid; i <= G; i += 256) gs_s[i] = g_gs[i];
    __syncthreads();
    const int n0 = gs_s[gq0];
    const int n1 = gs_s[gq1];

    for (int i = n0 + tid; i < n1; i += 256) m1s[i] = M1[i] * CI;
#pragma unroll
    for (int bb = 0; bb < 4; ++bb) {
        const float* shb = sh + (size_t)(b_base + bb) * NORD;
        for (int i = n0 + tid; i < n1; i += 256)
            coefs4[bb][i] = CG[i] * shb[M2[i]];
    }
    __syncthreads();

    const int b = b_base + bsub;
    const float* xb = x + (size_t)b * NORD * CI + c4;
    const float* cf = coefs4[bsub];

    for (int g = gq0; g < gq1; ++g) {
        float ax = 0.f, ay = 0.f, az = 0.f, aw = 0.f;
        const int e = gs_s[g + 1];
        for (int idx = gs_s[g]; idx < e; ++idx) {
            const float c = cf[idx];
            const float4 xv = *reinterpret_cast<const float4*>(xb + m1s[idx]);
            ax = fmaf(c, xv.x, ax);
            ay = fmaf(c, xv.y, ay);
            az = fmaf(c, xv.z, az);
            aw = fmaf(c, xv.w, aw);
        }
        __nv_bfloat162 h01 = __floats2bfloat162_rn(ax, ay);
        __nv_bfloat162 h23 = __floats2bfloat162_rn(az, aw);
        float lx = ax - __bfloat162float(__low2bfloat16(h01));
        float ly = ay - __bfloat162float(__high2bfloat16(h01));
        float lz = az - __bfloat162float(__low2bfloat16(h23));
        float lw = aw - __bfloat162float(__high2bfloat16(h23));
        __nv_bfloat162 l01 = __floats2bfloat162_rn(lx, ly);
        __nv_bfloat162 l23 = __floats2bfloat162_rn(lz, lw);

        size_t o = (((size_t)g * Bn + b) * 8 + (c4 >> 5)) * 64 + (c4 & 31);
        *reinterpret_cast<uint2*>(g_ax + o) =
            make_uint2(*(uint32_t*)&h01, *(uint32_t*)&h23);
        *reinterpret_cast<uint2*>(g_ax + o + 32) =
            make_uint2(*(uint32_t*)&l01, *(uint32_t*)&l23);
    }
}

// ---------------------------------------------------------------------------
// K3: mma.sync GEMM. Grid (Bn/64, CO/128, NORD), 256 threads (2m x 4n warps,
// warp tile 32x32). KT=32. Stage 24KB: A 8K | W 16K. 3-stage ring, one
// __syncthreads per stage. 3 CTAs/SM.
// ---------------------------------------------------------------------------
#define OFF_W       8192
#define STAGE_BYTES 24576
#define NSTAGE      3
#define SMEM_DYN    (NSTAGE * STAGE_BYTES + 1024)

__device__ __forceinline__ void load_stage(uint32_t st,
                                           const char* gA, const char* gW,
                                           int tid) {
    // A: 64 rows x 8 chunks of 16B (row = 128B interleaved hi|lo)
#pragma unroll
    for (int i = 0; i < 2; ++i) {
        int idx = tid + i * 256;
        int r = idx >> 3, c = idx & 7;
        cp16(st + SWZ(r * 128 + c * 16), gA + (size_t)r * 1024 + c * 16);
    }
    // W: 128 rows x 8 chunks
#pragma unroll
    for (int i = 0; i < 4; ++i) {
        int idx = tid + i * 256;
        int r = idx >> 3, c = idx & 7;
        cp16(st + OFF_W + SWZ(r * 128 + c * 16), gW + (size_t)r * 1024 + c * 16);
    }
}

__global__ __launch_bounds__(256, 3) void so3_mma(
    const int* __restrict__ l_ind,
    float* __restrict__ out,
    int Bn) {

    extern __shared__ char smem[];
    const uint32_t sb   = smem_u32(smem);
    const uint32_t base = (sb + 1023) & ~1023u;

    const int tid  = threadIdx.x;
    const int wid  = tid >> 5;
    const int lane = tid & 31;
    const int wm   = wid & 1;          // 2 m-warps (32 rows each)
    const int wn   = wid >> 1;         // 4 n-warps (32 cols each)

    const int b0  = blockIdx.x * 64;
    const int cob = blockIdx.y * 128;
    const int M   = c_morder[blockIdx.z];
    const int gbeg = g_mg[M];
    const int gend = g_mg[M + 1];
    const int T = (gend - gbeg) * 8;   // k-chunks of 32

    float acc[2][4][4];
#pragma unroll
    for (int i = 0; i < 2; ++i)
#pragma unroll
        for (int j = 0; j < 4; ++j)
#pragma unroll
            for (int q = 0; q < 4; ++q) acc[i][j][q] = 0.f;

    auto srcA = [&](int t) -> const char* {
        int g = gbeg + (t >> 3), kc = t & 7;
        return (const char*)g_ax + ((size_t)g * Bn + b0) * 1024 + kc * 128;
    };
    auto srcW = [&](int t) -> const char* {
        int g = gbeg + (t >> 3), kc = t & 7;
        int w = __ldg(l_ind + g);
        return (const char*)g_wx + ((size_t)w * CO + cob) * 1024 + kc * 128;
    };

    // prologue: stages 0 and 1 in flight (T >= 32 always)
    load_stage(base,                srcA(0), srcW(0), tid);
    CP_COMMIT();
    load_stage(base + STAGE_BYTES,  srcA(1), srcW(1), tid);
    CP_COMMIT();

    // ldmatrix lane addressing
    const int arow = wm * 32 + (lane & 15);
    const int acol = (lane >> 4) * 16;
    const int wrow = wn * 32 + (lane & 7) + ((lane >> 4) << 3);
    const int wcol = ((lane >> 3) & 1) * 16;

    int s_cur = 0;   // stage of tile t
    for (int t = 0; t < T; ++t) {
        CP_WAIT(1);                 // tile t's group complete
        __syncthreads();            // data visible; everyone done with t-1

        // load tile t+2 into the stage freed at iteration t-1
        if (t + 2 < T) {
            int s_nxt = s_cur + 2; if (s_nxt >= NSTAGE) s_nxt -= NSTAGE;
            load_stage(base + (uint32_t)s_nxt * STAGE_BYTES,
                       srcA(t + 2), srcW(t + 2), tid);
        }
        CP_COMMIT();                // keep group accounting aligned

        const uint32_t st = base + (uint32_t)s_cur * STAGE_BYTES;
        if (++s_cur == NSTAGE) s_cur = 0;

#pragma unroll
        for (int ks = 0; ks < 2; ++ks) {           // two k16 steps in KT=32
            const int kb = ks * 32;                // byte offset in hi half
            uint32_t ah[2][4], al[2][4];
#pragma unroll
            for (int mi = 0; mi < 2; ++mi) {
                uint32_t ad = st + SWZ((arow + mi * 16) * 128 + kb + acol);
                ldsm4(ah[mi], ad);
                ldsm4(al[mi], ad ^ 64);            // lo half of the row
            }
#pragma unroll
            for (int j = 0; j < 2; ++j) {          // two n16 chunks
                uint32_t whf[4], wlf[4];
                uint32_t wd = st + OFF_W + SWZ((wrow + j * 16) * 128 + kb + wcol);
                ldsm4(whf, wd);
                ldsm4(wlf, wd ^ 64);
#pragma unroll
                for (int mi = 0; mi < 2; ++mi)
#pragma unroll
                    for (int s = 0; s < 2; ++s) {
                        float* c = acc[mi][j * 2 + s];
                        mma16816(c, ah[mi], whf[s * 2], whf[s * 2 + 1]);
                        mma16816(c, al[mi], whf[s * 2], whf[s * 2 + 1]);
                        mma16816(c, ah[mi], wlf[s * 2], wlf[s * 2 + 1]);
                    }
            }
        }
    }

    // epilogue: out[b0+.., M, cob+..] written exactly once
#pragma unroll
    for (int mi = 0; mi < 2; ++mi) {
        const int m0 = b0 + wm * 32 + mi * 16 + (lane >> 2);
#pragma unroll
        for (int j = 0; j < 4; ++j) {
            const int n = cob + wn * 32 + j * 8 + (lane & 3) * 2;
            float* p0 = out + ((size_t)m0 * NORD + M) * CO + n;
            float* p1 = out + ((size_t)(m0 + 8) * NORD + M) * CO + n;
            *(float2*)p0 = make_float2(acc[mi][j][0], acc[mi][j][1]);
            *(float2*)p1 = make_float2(acc[mi][j][2], acc[mi][j][3]);
        }
    }
}

// ---------------------------------------------------------------------------
// Inputs: x, sh, weight, CG_vals, M1, M2, seg1, l_ind, seg2, num_orders_out
// ---------------------------------------------------------------------------
extern "C" void kernel_launch(void* const* d_in, const int* in_sizes, int n_in,
                              void* d_out, int out_size) {
    const float* x      = (const float*)d_in[0];
    const float* sh     = (const float*)d_in[1];
    const float* weight = (const float*)d_in[2];
    const float* CG     = (const float*)d_in[3];
    const int*   M1     = (const int*)d_in[4];
    const int*   M2     = (const int*)d_in[5];
    const int*   seg1   = (const int*)d_in[6];
    const int*   l_ind  = (const int*)d_in[7];
    const int*   seg2   = (const int*)d_in[8];
    float*       out    = (float*)d_out;

    const int nnz = in_sizes[4];
    const int G   = in_sizes[7];
    const int Bn  = in_sizes[1] / NORD;
    const int n_w = in_sizes[2] / (CI * CO);

    static bool attr_set = false;
    if (!attr_set) {
        cudaFuncSetAttribute(so3_mma, cudaFuncAttributeMaxDynamicSharedMemorySize, SMEM_DYN);
        attr_set = true;
    }

    setup_offsets<<<1, 256>>>(seg1, seg2, nnz, G);
    {
        dim3 grid(CO / 32, CI / 32, n_w);
        wsplit<<<grid, 256>>>(weight);
    }
    {
        dim3 grid(Bn / 4, 4);
        build_inter<<<grid, 256>>>(x, sh, CG, M1, M2, nnz, G, Bn);
    }
    {
        dim3 grid(Bn / 64, CO / 128, NORD);
        so3_mma<<<grid, 256, SMEM_DYN>>>(l_ind, out, Bn);
    }
}

// round 9
// speedup vs baseline: 1.3880x; 1.3798x over previous
#include <cuda_runtime.h>
#include <cuda_fp16.h>
#include <cstdint>

// ---------------------------------------------------------------------------
// SO3Linear (L=3, B=1024, C=256) via fp16 2-term split mma.sync GEMM.
//
//  K0 setup_offsets : contiguous range tables from seg1/seg2 (nondecreasing)
//  K1 wsplit        : W[w][ci][co] fp32 -> Wt{h,l}[w][co][ci] fp16 (hi+lo)
//  K2 build_inter   : inter[g][b][ci] fp32 -> A[g][b][ci] fp16 (single plane)
//  K3 so3_mma       : per CTA (64 b-rows, 128 co, order M):
//                     fp32 accum of sum_g [A@Wh + A@Wl]
//                     A quantization (~1.4e-4 RMS) dominates error; W ~2^-22.
//                     KT=64, 2-stage cp.async, 2 CTAs/SM, heavy-M-first.
// ---------------------------------------------------------------------------

#define NORD     16
#define CI       256
#define CO       256
#define G_MAX    156
#define NNZ_MAX  512
#define NW_MAX   40
#define B_MAX    1024

// ---- device scratch ----
__device__ __half g_af[(size_t)G_MAX * B_MAX * CI];           // A, single fp16 plane
__device__ __half g_wh[(size_t)NW_MAX * CO * CI];             // W hi (transposed)
__device__ __half g_wl[(size_t)NW_MAX * CO * CI];             // W lo (transposed)
__device__ int g_gs[G_MAX + 1];
__device__ int g_mg[NORD + 1];

// heavy-orders-first schedule (groups/M: l=2 ->11, l=3 ->10, l=1 ->9, l=0 ->4)
__constant__ int c_morder[NORD] = {4,5,6,7,8, 9,10,11,12,13,14,15, 1,2,3, 0};

#define SWZ(o) ((o) ^ (((o) >> 3) & 0x70))

__device__ __forceinline__ uint32_t smem_u32(const void* p) {
    uint32_t a;
    asm("{ .reg .u64 t; cvta.to.shared.u64 t, %1; cvt.u32.u64 %0, t; }" : "=r"(a) : "l"(p));
    return a;
}
__device__ __forceinline__ void cp16(uint32_t dst, const void* src) {
    asm volatile("cp.async.cg.shared.global [%0], [%1], 16;" :: "r"(dst), "l"(src) : "memory");
}
#define CP_COMMIT()  asm volatile("cp.async.commit_group;" ::: "memory")
#define CP_WAIT(N)   asm volatile("cp.async.wait_group %0;" :: "n"(N) : "memory")

__device__ __forceinline__ void ldsm4(uint32_t r[4], uint32_t addr) {
    asm volatile("ldmatrix.sync.aligned.m8n8.x4.shared.b16 {%0,%1,%2,%3}, [%4];"
                 : "=r"(r[0]), "=r"(r[1]), "=r"(r[2]), "=r"(r[3]) : "r"(addr));
}
__device__ __forceinline__ void mma16816(float c[4], const uint32_t a[4],
                                         uint32_t b0, uint32_t b1) {
    asm volatile(
        "mma.sync.aligned.m16n8k16.row.col.f32.f16.f16.f32 "
        "{%0,%1,%2,%3}, {%4,%5,%6,%7}, {%8,%9}, {%0,%1,%2,%3};"
        : "+f"(c[0]), "+f"(c[1]), "+f"(c[2]), "+f"(c[3])
        : "r"(a[0]), "r"(a[1]), "r"(a[2]), "r"(a[3]), "r"(b0), "r"(b1));
}

// ---------------------------------------------------------------------------
// K0: range tables
// ---------------------------------------------------------------------------
__global__ void setup_offsets(const int* __restrict__ seg1,
                              const int* __restrict__ seg2,
                              int nnz, int G) {
    int tid = threadIdx.x;
    for (int i = tid; i < nnz; i += blockDim.x) {
        if (i == 0) g_gs[seg1[0]] = 0;
        else if (seg1[i] != seg1[i - 1]) g_gs[seg1[i]] = i;
    }
    for (int i = tid; i < G; i += blockDim.x) {
        if (i == 0) g_mg[seg2[0]] = 0;
        else if (seg2[i] != seg2[i - 1]) g_mg[seg2[i]] = i;
    }
    if (tid == 0) { g_gs[G] = nnz; g_mg[NORD] = G; }
}

// ---------------------------------------------------------------------------
// K1: transpose + fp16 split weights: W[w][ci][co] -> Wt{h,l}[w][co][ci]
// ---------------------------------------------------------------------------
__global__ __launch_bounds__(256) void wsplit(const float* __restrict__ weight) {
    __shared__ float tile[32][33];
    const int w  = blockIdx.z;
    const int bx = blockIdx.x;   // co block
    const int by = blockIdx.y;   // ci block
    const int tx = threadIdx.x & 31;
    const int ty = threadIdx.x >> 5;

    const float* in = weight + (size_t)w * CI * CO;
#pragma unroll
    for (int j = 0; j < 4; ++j) {
        int r = ty + 8 * j;
        tile[r][tx] = in[(size_t)(by * 32 + r) * CO + bx * 32 + tx];
    }
    __syncthreads();
#pragma unroll
    for (int j = 0; j < 4; ++j) {
        int r = ty + 8 * j;
        float v = tile[tx][r];
        __half h = __float2half(v);
        float lo = v - __half2float(h);
        size_t o = ((size_t)w * CO + (bx * 32 + r)) * CI + by * 32 + tx;
        g_wh[o] = h;
        g_wl[o] = __float2half(lo);
    }
}

// ---------------------------------------------------------------------------
// K2: build inter (vectorized, g-split x4). Block = 4 b; thread owns 4 ci.
// Single fp16 output plane.
// ---------------------------------------------------------------------------
__global__ __launch_bounds__(256) void build_inter(
    const float* __restrict__ x,
    const float* __restrict__ sh,
    const float* __restrict__ CG,
    const int* __restrict__ M1,
    const int* __restrict__ M2,
    int nnz, int G, int Bn) {

    __shared__ float coefs4[4][NNZ_MAX];
    __shared__ int   m1s[NNZ_MAX];
    __shared__ int   gs_s[G_MAX + 1];

    const int b_base = blockIdx.x * 4;
    const int q      = blockIdx.y;
    const int tid    = threadIdx.x;
    const int bsub   = tid >> 6;
    const int c4     = (tid & 63) * 4;

    const int gq0 = (G * q) >> 2;
    const int gq1 = (G * (q + 1)) >> 2;

    for (int i = tid; i <= G; i += 256) gs_s[i] = g_gs[i];
    __syncthreads();
    const int n0 = gs_s[gq0];
    const int n1 = gs_s[gq1];

    for (int i = n0 + tid; i < n1; i += 256) m1s[i] = M1[i] * CI;
#pragma unroll
    for (int bb = 0; bb < 4; ++bb) {
        const float* shb = sh + (size_t)(b_base + bb) * NORD;
        for (int i = n0 + tid; i < n1; i += 256)
            coefs4[bb][i] = CG[i] * shb[M2[i]];
    }
    __syncthreads();

    const int b = b_base + bsub;
    const float* xb = x + (size_t)b * NORD * CI + c4;
    const float* cf = coefs4[bsub];

    for (int g = gq0; g < gq1; ++g) {
        float ax = 0.f, ay = 0.f, az = 0.f, aw = 0.f;
        const int e = gs_s[g + 1];
        for (int idx = gs_s[g]; idx < e; ++idx) {
            const float c = cf[idx];
            const float4 xv = *reinterpret_cast<const float4*>(xb + m1s[idx]);
            ax = fmaf(c, xv.x, ax);
            ay = fmaf(c, xv.y, ay);
            az = fmaf(c, xv.z, az);
            aw = fmaf(c, xv.w, aw);
        }
        __half2 h01 = __floats2half2_rn(ax, ay);
        __half2 h23 = __floats2half2_rn(az, aw);
        size_t o = ((size_t)g * Bn + b) * CI + c4;
        *reinterpret_cast<uint2*>(g_af + o) =
            make_uint2(*(uint32_t*)&h01, *(uint32_t*)&h23);
    }
}

// ---------------------------------------------------------------------------
// K3: mma.sync GEMM. Grid (Bn/64, CO/128, NORD), 256 threads (2m x 4n warps,
// warp tile 32x32). Block tile 64(b) x 128(co), KT=64.
// Stage 40KB: A 8K | Wh 16K | Wl 16K. Double buffered -> 80KB, 2 CTAs/SM.
// ---------------------------------------------------------------------------
#define KT          64
#define OFF_WH      8192
#define OFF_WL      24576
#define STAGE_BYTES 40960
#define SMEM_DYN    (2 * STAGE_BYTES + 1024)

__device__ __forceinline__ void load_stage(uint32_t st,
                                           const char* gA,
                                           const char* gWh, const char* gWl,
                                           int tid) {
    // A: 64 rows x 8 chunks of 16B (row = 128B = 64 fp16 of this k-slab)
#pragma unroll
    for (int i = 0; i < 2; ++i) {
        int idx = tid + i * 256;
        int r = idx >> 3, c = idx & 7;
        uint32_t so = SWZ(r * 128 + c * 16);
        cp16(st + so, gA + (size_t)r * (CI * 2) + c * 16);
    }
    // W planes: 128 rows x 8 chunks each
#pragma unroll
    for (int i = 0; i < 4; ++i) {
        int idx = tid + i * 256;
        int r = idx >> 3, c = idx & 7;
        uint32_t so = SWZ(r * 128 + c * 16);
        size_t go = (size_t)r * (CI * 2) + c * 16;
        cp16(st + OFF_WH + so, gWh + go);
        cp16(st + OFF_WL + so, gWl + go);
    }
}

__global__ __launch_bounds__(256, 2) void so3_mma(
    const int* __restrict__ l_ind,
    float* __restrict__ out,
    int Bn) {

    extern __shared__ char smem[];
    const uint32_t sb   = smem_u32(smem);
    const uint32_t base = (sb + 1023) & ~1023u;

    const int tid  = threadIdx.x;
    const int wid  = tid >> 5;
    const int lane = tid & 31;
    const int wm   = wid & 1;          // 2 m-warps (32 rows each)
    const int wn   = wid >> 1;         // 4 n-warps (32 cols each)

    const int b0  = blockIdx.x * 64;
    const int cob = blockIdx.y * 128;
    const int M   = c_morder[blockIdx.z];
    const int gbeg = g_mg[M];
    const int gend = g_mg[M + 1];
    const int T = (gend - gbeg) * (CI / KT);   // k-tiles (4 per group)

    float acc[2][4][4];
#pragma unroll
    for (int i = 0; i < 2; ++i)
#pragma unroll
        for (int j = 0; j < 4; ++j)
#pragma unroll
            for (int q = 0; q < 4; ++q) acc[i][j][q] = 0.f;

    auto srcA = [&](int t) -> const char* {
        int g = gbeg + (t >> 2), kc = t & 3;
        return (const char*)g_af + (((size_t)g * Bn + b0) * CI + kc * KT) * 2;
    };
    auto srcWh = [&](int t) -> const char* {
        int g = gbeg + (t >> 2), kc = t & 3;
        int w = __ldg(l_ind + g);
        return (const char*)g_wh + (((size_t)w * CO + cob) * CI + kc * KT) * 2;
    };
    auto srcWl = [&](int t) -> const char* {
        int g = gbeg + (t >> 2), kc = t & 3;
        int w = __ldg(l_ind + g);
        return (const char*)g_wl + (((size_t)w * CO + cob) * CI + kc * KT) * 2;
    };

    // prologue
    load_stage(base, srcA(0), srcWh(0), srcWl(0), tid);
    CP_COMMIT();

    // ldmatrix lane addressing
    const int arow = wm * 32 + (lane & 15);
    const int acol = (lane >> 4) * 16;
    const int wrow = wn * 32 + (lane & 7) + ((lane >> 4) << 3);
    const int wcol = ((lane >> 3) & 1) * 16;

    for (int t = 0; t < T; ++t) {
        const uint32_t st = base + (uint32_t)(t & 1) * STAGE_BYTES;

        if (t + 1 < T) {
            const uint32_t stn = base + (uint32_t)((t + 1) & 1) * STAGE_BYTES;
            load_stage(stn, srcA(t + 1), srcWh(t + 1), srcWl(t + 1), tid);
            CP_COMMIT();
            CP_WAIT(1);
        } else {
            CP_WAIT(0);
        }
        __syncthreads();

#pragma unroll
        for (int ks = 0; ks < KT / 16; ++ks) {
            const int kb = ks * 32;                // 16 fp16 = 32B
            uint32_t af[2][4];
#pragma unroll
            for (int mi = 0; mi < 2; ++mi) {
                uint32_t ad = st + SWZ((arow + mi * 16) * 128 + kb + acol);
                ldsm4(af[mi], ad);
            }
#pragma unroll
            for (int j = 0; j < 2; ++j) {          // two n16 chunks
                uint32_t whf[4], wlf[4];
                uint32_t wd = st + SWZ((wrow + j * 16) * 128 + kb + wcol);
                ldsm4(whf, wd + OFF_WH);
                ldsm4(wlf, wd + OFF_WL);
#pragma unroll
                for (int mi = 0; mi < 2; ++mi)
#pragma unroll
                    for (int s = 0; s < 2; ++s) {
                        float* c = acc[mi][j * 2 + s];
                        mma16816(c, af[mi], whf[s * 2], whf[s * 2 + 1]);
                        mma16816(c, af[mi], wlf[s * 2], wlf[s * 2 + 1]);
                    }
            }
        }
        __syncthreads();
    }

    // epilogue: out[b0+.., M, cob+..] written exactly once
#pragma unroll
    for (int mi = 0; mi < 2; ++mi) {
        const int m0 = b0 + wm * 32 + mi * 16 + (lane >> 2);
#pragma unroll
        for (int j = 0; j < 4; ++j) {
            const int n = cob + wn * 32 + j * 8 + (lane & 3) * 2;
            float* p0 = out + ((size_t)m0 * NORD + M) * CO + n;
            float* p1 = out + ((size_t)(m0 + 8) * NORD + M) * CO + n;
            *(float2*)p0 = make_float2(acc[mi][j][0], acc[mi][j][1]);
            *(float2*)p1 = make_float2(acc[mi][j][2], acc[mi][j][3]);
        }
    }
}

// ---------------------------------------------------------------------------
// Inputs: x, sh, weight, CG_vals, M1, M2, seg1, l_ind, seg2, num_orders_out
// ---------------------------------------------------------------------------
extern "C" void kernel_launch(void* const* d_in, const int* in_sizes, int n_in,
                              void* d_out, int out_size) {
    const float* x      = (const float*)d_in[0];
    const float* sh     = (const float*)d_in[1];
    const float* weight = (const float*)d_in[2];
    const float* CG     = (const float*)d_in[3];
    const int*   M1     = (const int*)d_in[4];
    const int*   M2     = (const int*)d_in[5];
    const int*   seg1   = (const int*)d_in[6];
    const int*   l_ind  = (const int*)d_in[7];
    const int*   seg2   = (const int*)d_in[8];
    float*       out    = (float*)d_out;

    const int nnz = in_sizes[4];
    const int G   = in_sizes[7];
    const int Bn  = in_sizes[1] / NORD;
    const int n_w = in_sizes[2] / (CI * CO);

    static bool attr_set = false;
    if (!attr_set) {
        cudaFuncSetAttribute(so3_mma, cudaFuncAttributeMaxDynamicSharedMemorySize, SMEM_DYN);
        attr_set = true;
    }

    setup_offsets<<<1, 256>>>(seg1, seg2, nnz, G);
    {
        dim3 grid(CO / 32, CI / 32, n_w);
        wsplit<<<grid, 256>>>(weight);
    }
    {
        dim3 grid(Bn / 4, 4);
        build_inter<<<grid, 256>>>(x, sh, CG, M1, M2, nnz, G, Bn);
    }
    {
        dim3 grid(Bn / 64, CO / 128, NORD);
        so3_mma<<<grid, 256, SMEM_DYN>>>(l_ind, out, Bn);
    }
}

// round 10
// speedup vs baseline: 2.0579x; 1.4826x over previous
#include <cuda_runtime.h>
#include <cuda_fp16.h>
#include <cstdint>

// ---------------------------------------------------------------------------
// SO3Linear (L=3, B=1024, C=256) via pure-fp16 mma.sync GEMM (1 term).
//
//  K0 setup_offsets : contiguous range tables from seg1/seg2 (nondecreasing)
//  K1 wsplit        : W[w][ci][co] fp32 -> Wt[w][co][ci] fp16
//  K2 build_inter   : inter[g][b][ci] fp32 -> A[g][b][ci] fp16
//  K3 so3_mma       : per CTA (64 b-rows, 128 co, order M): fp32 accum of
//                     sum_g A@W. 4 warps, warp tile 32x64 (minimizes SMEM
//                     port B/MAC), KT=64, 2-stage cp.async, 4 CTAs/SM.
//  Quantization err: A ~2.1e-4 + W ~2.1e-4 (indep) => ~3e-4 << 1e-3.
// ---------------------------------------------------------------------------

#define NORD     16
#define CI       256
#define CO       256
#define G_MAX    156
#define NNZ_MAX  512
#define NW_MAX   40
#define B_MAX    1024

// ---- device scratch ----
__device__ __half g_af[(size_t)G_MAX * B_MAX * CI];   // A fp16
__device__ __half g_wf[(size_t)NW_MAX * CO * CI];     // W fp16 (transposed)
__device__ int g_gs[G_MAX + 1];
__device__ int g_mg[NORD + 1];

// heavy-orders-first schedule (groups/M: l=2 ->11, l=3 ->10, l=1 ->9, l=0 ->4)
__constant__ int c_morder[NORD] = {4,5,6,7,8, 9,10,11,12,13,14,15, 1,2,3, 0};

#define SWZ(o) ((o) ^ (((o) >> 3) & 0x70))

__device__ __forceinline__ uint32_t smem_u32(const void* p) {
    uint32_t a;
    asm("{ .reg .u64 t; cvta.to.shared.u64 t, %1; cvt.u32.u64 %0, t; }" : "=r"(a) : "l"(p));
    return a;
}
__device__ __forceinline__ void cp16(uint32_t dst, const void* src) {
    asm volatile("cp.async.cg.shared.global [%0], [%1], 16;" :: "r"(dst), "l"(src) : "memory");
}
#define CP_COMMIT()  asm volatile("cp.async.commit_group;" ::: "memory")
#define CP_WAIT(N)   asm volatile("cp.async.wait_group %0;" :: "n"(N) : "memory")

__device__ __forceinline__ void ldsm4(uint32_t r[4], uint32_t addr) {
    asm volatile("ldmatrix.sync.aligned.m8n8.x4.shared.b16 {%0,%1,%2,%3}, [%4];"
                 : "=r"(r[0]), "=r"(r[1]), "=r"(r[2]), "=r"(r[3]) : "r"(addr));
}
__device__ __forceinline__ void mma16816(float c[4], const uint32_t a[4],
                                         uint32_t b0, uint32_t b1) {
    asm volatile(
        "mma.sync.aligned.m16n8k16.row.col.f32.f16.f16.f32 "
        "{%0,%1,%2,%3}, {%4,%5,%6,%7}, {%8,%9}, {%0,%1,%2,%3};"
        : "+f"(c[0]), "+f"(c[1]), "+f"(c[2]), "+f"(c[3])
        : "r"(a[0]), "r"(a[1]), "r"(a[2]), "r"(a[3]), "r"(b0), "r"(b1));
}

// ---------------------------------------------------------------------------
// K0: range tables
// ---------------------------------------------------------------------------
__global__ void setup_offsets(const int* __restrict__ seg1,
                              const int* __restrict__ seg2,
                              int nnz, int G) {
    int tid = threadIdx.x;
    for (int i = tid; i < nnz; i += blockDim.x) {
        if (i == 0) g_gs[seg1[0]] = 0;
        else if (seg1[i] != seg1[i - 1]) g_gs[seg1[i]] = i;
    }
    for (int i = tid; i < G; i += blockDim.x) {
        if (i == 0) g_mg[seg2[0]] = 0;
        else if (seg2[i] != seg2[i - 1]) g_mg[seg2[i]] = i;
    }
    if (tid == 0) { g_gs[G] = nnz; g_mg[NORD] = G; }
}

// ---------------------------------------------------------------------------
// K1: transpose weights to fp16: W[w][ci][co] -> Wt[w][co][ci]
// ---------------------------------------------------------------------------
__global__ __launch_bounds__(256) void wsplit(const float* __restrict__ weight) {
    __shared__ float tile[32][33];
    const int w  = blockIdx.z;
    const int bx = blockIdx.x;   // co block
    const int by = blockIdx.y;   // ci block
    const int tx = threadIdx.x & 31;
    const int ty = threadIdx.x >> 5;

    const float* in = weight + (size_t)w * CI * CO;
#pragma unroll
    for (int j = 0; j < 4; ++j) {
        int r = ty + 8 * j;
        tile[r][tx] = in[(size_t)(by * 32 + r) * CO + bx * 32 + tx];
    }
    __syncthreads();
#pragma unroll
    for (int j = 0; j < 4; ++j) {
        int r = ty + 8 * j;
        float v = tile[tx][r];
        size_t o = ((size_t)w * CO + (bx * 32 + r)) * CI + by * 32 + tx;
        g_wf[o] = __float2half(v);
    }
}

// ---------------------------------------------------------------------------
// K2: build inter (vectorized, g-split x4). Block = 4 b; thread owns 4 ci.
// ---------------------------------------------------------------------------
__global__ __launch_bounds__(256) void build_inter(
    const float* __restrict__ x,
    const float* __restrict__ sh,
    const float* __restrict__ CG,
    const int* __restrict__ M1,
    const int* __restrict__ M2,
    int nnz, int G, int Bn) {

    __shared__ float coefs4[4][NNZ_MAX];
    __shared__ int   m1s[NNZ_MAX];
    __shared__ int   gs_s[G_MAX + 1];

    const int b_base = blockIdx.x * 4;
    const int q      = blockIdx.y;
    const int tid    = threadIdx.x;
    const int bsub   = tid >> 6;
    const int c4     = (tid & 63) * 4;

    const int gq0 = (G * q) >> 2;
    const int gq1 = (G * (q + 1)) >> 2;

    for (int i = tid; i <= G; i += 256) gs_s[i] = g_gs[i];
    __syncthreads();
    const int n0 = gs_s[gq0];
    const int n1 = gs_s[gq1];

    for (int i = n0 + tid; i < n1; i += 256) m1s[i] = M1[i] * CI;
#pragma unroll
    for (int bb = 0; bb < 4; ++bb) {
        const float* shb = sh + (size_t)(b_base + bb) * NORD;
        for (int i = n0 + tid; i < n1; i += 256)
            coefs4[bb][i] = CG[i] * shb[M2[i]];
    }
    __syncthreads();

    const int b = b_base + bsub;
    const float* xb = x + (size_t)b * NORD * CI + c4;
    const float* cf = coefs4[bsub];

    for (int g = gq0; g < gq1; ++g) {
        float ax = 0.f, ay = 0.f, az = 0.f, aw = 0.f;
        const int e = gs_s[g + 1];
        for (int idx = gs_s[g]; idx < e; ++idx) {
            const float c = cf[idx];
            const float4 xv = *reinterpret_cast<const float4*>(xb + m1s[idx]);
            ax = fmaf(c, xv.x, ax);
            ay = fmaf(c, xv.y, ay);
            az = fmaf(c, xv.z, az);
            aw = fmaf(c, xv.w, aw);
        }
        __half2 h01 = __floats2half2_rn(ax, ay);
        __half2 h23 = __floats2half2_rn(az, aw);
        size_t o = ((size_t)g * Bn + b) * CI + c4;
        *reinterpret_cast<uint2*>(g_af + o) =
            make_uint2(*(uint32_t*)&h01, *(uint32_t*)&h23);
    }
}

// ---------------------------------------------------------------------------
// K3: mma.sync GEMM. Grid (Bn/64, CO/128, NORD), 128 threads (4 warps:
// 2m x 2n, warp tile 32x64). Block tile 64(b) x 128(co), KT=64.
// Stage 24KB: A 8K | W 16K. Double buffered -> 48KB+1K, 4 CTAs/SM.
// ---------------------------------------------------------------------------
#define KT          64
#define OFF_W       8192
#define STAGE_BYTES 24576
#define SMEM_DYN    (2 * STAGE_BYTES + 1024)

__device__ __forceinline__ void load_stage(uint32_t st,
                                           const char* gA, const char* gW,
                                           int tid) {
    // A: 64 rows x 8 chunks of 16B (row = 128B = 64 fp16 of this k-slab)
#pragma unroll
    for (int i = 0; i < 4; ++i) {
        int idx = tid + i * 128;
        int r = idx >> 3, c = idx & 7;
        cp16(st + SWZ(r * 128 + c * 16), gA + (size_t)r * (CI * 2) + c * 16);
    }
    // W: 128 rows x 8 chunks
#pragma unroll
    for (int i = 0; i < 8; ++i) {
        int idx = tid + i * 128;
        int r = idx >> 3, c = idx & 7;
        cp16(st + OFF_W + SWZ(r * 128 + c * 16), gW + (size_t)r * (CI * 2) + c * 16);
    }
}

__global__ __launch_bounds__(128, 4) void so3_mma(
    const int* __restrict__ l_ind,
    float* __restrict__ out,
    int Bn) {

    extern __shared__ char smem[];
    const uint32_t sb   = smem_u32(smem);
    const uint32_t base = (sb + 1023) & ~1023u;

    const int tid  = threadIdx.x;
    const int wid  = tid >> 5;
    const int lane = tid & 31;
    const int wm   = wid & 1;          // 2 m-warps (32 rows each)
    const int wn   = wid >> 1;         // 2 n-warps (64 cols each)

    const int b0  = blockIdx.x * 64;
    const int cob = blockIdx.y * 128;
    const int M   = c_morder[blockIdx.z];
    const int gbeg = g_mg[M];
    const int gend = g_mg[M + 1];
    const int T = (gend - gbeg) * (CI / KT);   // k-tiles (4 per group)

    // acc[mi 0..1][n8 0..7][4] = 64 regs
    float acc[2][8][4];
#pragma unroll
    for (int i = 0; i < 2; ++i)
#pragma unroll
        for (int j = 0; j < 8; ++j)
#pragma unroll
            for (int q = 0; q < 4; ++q) acc[i][j][q] = 0.f;

    auto srcA = [&](int t) -> const char* {
        int g = gbeg + (t >> 2), kc = t & 3;
        return (const char*)g_af + (((size_t)g * Bn + b0) * CI + kc * KT) * 2;
    };
    auto srcW = [&](int t) -> const char* {
        int g = gbeg + (t >> 2), kc = t & 3;
        int w = __ldg(l_ind + g);
        return (const char*)g_wf + (((size_t)w * CO + cob) * CI + kc * KT) * 2;
    };

    // prologue
    load_stage(base, srcA(0), srcW(0), tid);
    CP_COMMIT();

    // ldmatrix lane addressing
    const int arow = wm * 32 + (lane & 15);
    const int acol = (lane >> 4) * 16;
    const int wrow = wn * 64 + (lane & 7) + ((lane >> 4) << 3);
    const int wcol = ((lane >> 3) & 1) * 16;

    for (int t = 0; t < T; ++t) {
        const uint32_t st = base + (uint32_t)(t & 1) * STAGE_BYTES;

        if (t + 1 < T) {
            const uint32_t stn = base + (uint32_t)((t + 1) & 1) * STAGE_BYTES;
            load_stage(stn, srcA(t + 1), srcW(t + 1), tid);
            CP_COMMIT();
            CP_WAIT(1);
        } else {
            CP_WAIT(0);
        }
        __syncthreads();

#pragma unroll
        for (int ks = 0; ks < KT / 16; ++ks) {
            const int kb = ks * 32;                // 16 fp16 = 32B
            uint32_t af[2][4];
#pragma unroll
            for (int mi = 0; mi < 2; ++mi) {
                uint32_t ad = st + SWZ((arow + mi * 16) * 128 + kb + acol);
                ldsm4(af[mi], ad);
            }
#pragma unroll
            for (int j = 0; j < 4; ++j) {          // four n16 chunks (64 cols)
                uint32_t wf[4];
                uint32_t wd = st + OFF_W + SWZ((wrow + j * 16) * 128 + kb + wcol);
                ldsm4(wf, wd);
#pragma unroll
                for (int mi = 0; mi < 2; ++mi)
#pragma unroll
                    for (int s = 0; s < 2; ++s)
                        mma16816(acc[mi][j * 2 + s], af[mi], wf[s * 2], wf[s * 2 + 1]);
            }
        }
        __syncthreads();
    }

    // epilogue: out[b0+.., M, cob+..] written exactly once
#pragma unroll
    for (int mi = 0; mi < 2; ++mi) {
        const int m0 = b0 + wm * 32 + mi * 16 + (lane >> 2);
#pragma unroll
        for (int j = 0; j < 8; ++j) {
            const int n = cob + wn * 64 + j * 8 + (lane & 3) * 2;
            float* p0 = out + ((size_t)m0 * NORD + M) * CO + n;
            float* p1 = out + ((size_t)(m0 + 8) * NORD + M) * CO + n;
            *(float2*)p0 = make_float2(acc[mi][j][0], acc[mi][j][1]);
            *(float2*)p1 = make_float2(acc[mi][j][2], acc[mi][j][3]);
        }
    }
}

// ---------------------------------------------------------------------------
// Inputs: x, sh, weight, CG_vals, M1, M2, seg1, l_ind, seg2, num_orders_out
// ---------------------------------------------------------------------------
extern "C" void kernel_launch(void* const* d_in, const int* in_sizes, int n_in,
                              void* d_out, int out_size) {
    const float* x      = (const float*)d_in[0];
    const float* sh     = (const float*)d_in[1];
    const float* weight = (const float*)d_in[2];
    const float* CG     = (const float*)d_in[3];
    const int*   M1     = (const int*)d_in[4];
    const int*   M2     = (const int*)d_in[5];
    const int*   seg1   = (const int*)d_in[6];
    const int*   l_ind  = (const int*)d_in[7];
    const int*   seg2   = (const int*)d_in[8];
    float*       out    = (float*)d_out;

    const int nnz = in_sizes[4];
    const int G   = in_sizes[7];
    const int Bn  = in_sizes[1] / NORD;
    const int n_w = in_sizes[2] / (CI * CO);

    static bool attr_set = false;
    if (!attr_set) {
        cudaFuncSetAttribute(so3_mma, cudaFuncAttributeMaxDynamicSharedMemorySize, SMEM_DYN);
        attr_set = true;
    }

    setup_offsets<<<1, 256>>>(seg1, seg2, nnz, G);
    {
        dim3 grid(CO / 32, CI / 32, n_w);
        wsplit<<<grid, 256>>>(weight);
    }
    {
        dim3 grid(Bn / 4, 4);
        build_inter<<<grid, 256>>>(x, sh, CG, M1, M2, nnz, G, Bn);
    }
    {
        dim3 grid(Bn / 64, CO / 128, NORD);
        so3_mma<<<grid, 128, SMEM_DYN>>>(l_ind, out, Bn);
    }
}